// round 14
// baseline (speedup 1.0000x reference)
#include <cuda_runtime.h>

// Fused gauss-attention, N=262144, T=1, S=9, E=32, H=2, HD=16.
// Round 14: round-12 code (best-equivalent: scalar butterflies, t-fold)
// + gw exps hoisted (kept from r13, the packed butterflies rejected)
// + single-variable launch-config experiment: 6 blocks/SM (<=85 regs,
// grid 888) to test whether the 72-reg cap was constraining ILP.

#define SEQ 9
typedef unsigned long long u64;

#define PACK2(out, lo, hi) \
    asm("mov.b64 %0, {%1, %2};" : "=l"(out) : "f"(lo), "f"(hi))
#define UNPACK2(lo, hi, in) \
    asm("mov.b64 {%0, %1}, %2;" : "=f"(lo), "=f"(hi) : "l"(in))
#define FMA2(d, a, b, c) \
    asm("fma.rn.f32x2 %0, %1, %2, %3;" : "=l"(d) : "l"(a), "l"(b), "l"(c))
#define MUL2(d, a, b) \
    asm("mul.rn.f32x2 %0, %1, %2;" : "=l"(d) : "l"(a), "l"(b))

// Block layout (non-duplicated), per head 1024 floats:
//   idx = h*1024 + j*128 + gi*32 + o*4 + c,  value = Mat[4o+gi][4j+c]
__device__ float g_PB[2048];
__device__ float g_MB[2048];
__device__ float g_rb[2 * 32];
__device__ float g_u[2 * 32];
__device__ float g_t0[2];
__device__ float g_D[32];

__global__ void prep_kernel(const float* __restrict__ ipw,
                            const float* __restrict__ ipb,
                            const float* __restrict__ opw,
                            const float* __restrict__ opb) {
    const float* wq = ipw;
    const float* wk = ipw + 1024;
    const float* wv = ipw + 2048;
    const float* bq = ipb;
    const float* bk = ipb + 32;
    const float* bv = ipb + 64;
    int tid = threadIdx.x;

    for (int idx = tid; idx < 2048; idx += blockDim.x) {
        int h = idx >> 10;
        int a = (idx >> 5) & 31;   // row (P: g, M: f)
        int c = idx & 31;          // col (P: e, M: g)
        float accP = 0.f, accM = 0.f;
        #pragma unroll
        for (int d = 0; d < 16; d++) {
            int f = h * 16 + d;
            accP += wk[f * 32 + a] * wq[f * 32 + c];
            accM += opw[a * 32 + f] * wv[f * 32 + c];
        }
        int blk = h * 1024 + (c >> 2) * 128 + (a & 3) * 32 + (a >> 2) * 4 + (c & 3);
        g_PB[blk] = 0.25f * accP;
        g_MB[blk] = accM;
    }
    if (tid < 64) {
        int h = tid >> 5, j = tid & 31;
        float arb = 0.f, au = 0.f;
        #pragma unroll
        for (int d = 0; d < 16; d++) {
            int f = h * 16 + d;
            arb += bq[f] * wk[f * 32 + j];
            au  += wq[f * 32 + j] * bk[f];
        }
        g_rb[tid] = 0.25f * arb;
        g_u[tid]  = 0.25f * au;
    }
    if (tid < 32) {
        float acc = opb[tid];
        #pragma unroll
        for (int e = 0; e < 32; e++) acc += opw[tid * 32 + e] * bv[e];
        g_D[tid] = acc;
    }
    if (tid < 2) {
        float acc = 0.f;
        #pragma unroll
        for (int d = 0; d < 16; d++) acc += bq[tid * 16 + d] * bk[tid * 16 + d];
        g_t0[tid] = 0.25f * acc;
    }
}

__global__ void __launch_bounds__(128, 6)
attn_kernel(const float* __restrict__ query, const float* __restrict__ key,
            const float* __restrict__ value, const float* __restrict__ gauss,
            float* __restrict__ out, int n) {
    __shared__ __align__(16) float sPB[2048];
    __shared__ __align__(16) float sMB[2048];
    // Per-warp staging (natural layout): region0 = q, reused as vs-head0;
    // region1 = vs-head1. Layout [quad][trow][36] per region.
    __shared__ __align__(16) float sStage[4][576];
    __shared__ __align__(16) float sGauss[4][72];
    __shared__ float srb[64];
    __shared__ float su[64];
    __shared__ float st0[2];
    __shared__ float sD[32];

    int tid = threadIdx.x;
    for (int i = tid; i < 2048; i += 128) {
        sPB[i] = g_PB[i];
        sMB[i] = g_MB[i];
    }
    if (tid < 64) { srb[tid] = g_rb[tid]; su[tid] = g_u[tid]; }
    if (tid < 32) sD[tid] = g_D[tid];
    if (tid < 2)  st0[tid] = g_t0[tid];
    __syncthreads();

    const int lane = tid & 31;
    const int o    = lane & 7;      // feature-chunk owner within octet
    const int trow = lane >> 3;     // which batch of the quad
    const int warp = tid >> 5;
    float* st0reg = sStage[warp];         // q / vs-head0: [quad][trow][36]
    float* st1reg = sStage[warp] + 288;   // vs-head1
    float* gb     = sGauss[warp];

    const float4* qptr = (const float4*)query;
    const float4* kptr = (const float4*)key;
    const ulonglong2* vptr = (const ulonglong2*)value;
    float4* optr = (float4*)out;

    const int ngroups = (n + 7) >> 3;
    const int warp_g  = (blockIdx.x * 128 + tid) >> 5;
    const int wstep   = (gridDim.x * 128) >> 5;

    for (int grp = warp_g; grp < ngroups; grp += wstep) {
        int bA = grp * 8 + trow;
        int bB = bA + 4;
        int blA = bA < n ? bA : n - 1;
        int blB = bB < n ? bB : n - 1;

        // ---- stage gauss for the whole group: 72 contiguous floats ----
        __syncwarp();
        {
            int rem9 = n * SEQ - grp * 72;
            if (rem9 >= 72) {
                if (lane < 18)
                    *(float4*)&gb[lane * 4] =
                        *(const float4*)(gauss + (size_t)grp * 72 + lane * 4);
            } else {
                for (int i = lane; i < 72; i += 32)
                    gb[i] = gauss[(size_t)grp * 72 + (i < rem9 ? i : rem9 - 1)];
            }
        }

        // ---- load q chunks (coalesced) ----
        float4 qA = qptr[(size_t)blA * 8 + o];
        float4 qB = qptr[(size_t)blB * 8 + o];

        // per-lane t partials (own chunk); lane o==0 also carries st0 constant
        float c0 = (o == 0) ? st0[0] : 0.0f;
        float c1 = (o == 0) ? st0[1] : 0.0f;
        float tA0 = c0 + su[o * 4 + 0] * qA.x + su[o * 4 + 1] * qA.y
                  + su[o * 4 + 2] * qA.z + su[o * 4 + 3] * qA.w;
        float tA1 = c1 + su[32 + o * 4 + 0] * qA.x + su[32 + o * 4 + 1] * qA.y
                  + su[32 + o * 4 + 2] * qA.z + su[32 + o * 4 + 3] * qA.w;
        float tB0 = c0 + su[o * 4 + 0] * qB.x + su[o * 4 + 1] * qB.y
                  + su[o * 4 + 2] * qB.z + su[o * 4 + 3] * qB.w;
        float tB1 = c1 + su[32 + o * 4 + 0] * qB.x + su[32 + o * 4 + 1] * qB.y
                  + su[32 + o * 4 + 2] * qB.z + su[32 + o * 4 + 3] * qB.w;

        // ---- stage q (natural layout) ----
        *(float4*)&st0reg[trow * 36 + o * 4]       = qA;   // quad A
        *(float4*)&st0reg[144 + trow * 36 + o * 4] = qB;   // quad B
        __syncwarp();

        // ---- P matvec: f32x2 over e-pairs, weights non-duplicated ----
        u64 pA0[4], pA1[4], pB0[4], pB1[4];
        #pragma unroll
        for (int gi = 0; gi < 4; gi++) {
            float b0 = srb[o * 4 + gi];
            float b1 = srb[32 + o * 4 + gi];
            PACK2(pA0[gi], b0, 0.0f);  PACK2(pB0[gi], b0, 0.0f);
            PACK2(pA1[gi], b1, 0.0f);  PACK2(pB1[gi], b1, 0.0f);
        }
        #pragma unroll
        for (int j = 0; j < 8; j++) {
            ulonglong2 QA = *(const ulonglong2*)&st0reg[trow * 36 + j * 4];
            ulonglong2 QB = *(const ulonglong2*)&st0reg[144 + trow * 36 + j * 4];
            #pragma unroll
            for (int gi = 0; gi < 4; gi++) {
                ulonglong2 W0 = *(const ulonglong2*)&sPB[j * 128 + gi * 32 + o * 4];
                ulonglong2 W1 = *(const ulonglong2*)&sPB[1024 + j * 128 + gi * 32 + o * 4];
                FMA2(pA0[gi], W0.x, QA.x, pA0[gi]);
                FMA2(pA0[gi], W0.y, QA.y, pA0[gi]);
                FMA2(pB0[gi], W0.x, QB.x, pB0[gi]);
                FMA2(pB0[gi], W0.y, QB.y, pB0[gi]);
                FMA2(pA1[gi], W1.x, QA.x, pA1[gi]);
                FMA2(pA1[gi], W1.y, QA.y, pA1[gi]);
                FMA2(pB1[gi], W1.x, QB.x, pB1[gi]);
                FMA2(pB1[gi], W1.y, QB.y, pB1[gi]);
            }
        }
        float rA0[4], rA1[4], rB0[4], rB1[4];
        #pragma unroll
        for (int gi = 0; gi < 4; gi++) {
            float lo, hi;
            UNPACK2(lo, hi, pA0[gi]); rA0[gi] = lo + hi;
            UNPACK2(lo, hi, pA1[gi]); rA1[gi] = lo + hi;
            UNPACK2(lo, hi, pB0[gi]); rB0[gi] = lo + hi;
            UNPACK2(lo, hi, pB1[gi]); rB1[gi] = lo + hi;
        }

        // ---- per-quad: K stream -> logits -> softmax -> V stream ----
        u64 vA0[2], vA1[2], vB0[2], vB1[2];
        #pragma unroll
        for (int half = 0; half < 2; half++) {
            int bl = half ? blB : blA;
            int grow = half * 4 + trow;       // batch index within group
            float r0x = half ? rB0[0] : rA0[0];
            float r0y = half ? rB0[1] : rA0[1];
            float r0z = half ? rB0[2] : rA0[2];
            float r0w = half ? rB0[3] : rA0[3];
            float r1x = half ? rB1[0] : rA1[0];
            float r1y = half ? rB1[1] : rA1[1];
            float r1z = half ? rB1[2] : rA1[2];
            float r1w = half ? rB1[3] : rA1[3];
            float t0 = half ? tB0 : tA0;      // per-lane partial (incl. st0 on o==0)
            float t1 = half ? tB1 : tA1;

            // gw exps hoisted off the per-s critical path (overlap K LDGs)
            float gw[SEQ];
            #pragma unroll
            for (int s = 0; s < SEQ; s++)
                gw[s] = __expf(-10.0f * gb[grow * SEQ + s]);

            float l0[SEQ], l1[SEQ];
            #pragma unroll
            for (int s = 0; s < SEQ; s++) {
                float4 kv = kptr[(size_t)bl * 72 + s * 8 + o];
                float d0 = fmaf(r0x, kv.x, t0);   // t folded pre-reduction
                d0 = fmaf(r0y, kv.y, d0);
                d0 = fmaf(r0z, kv.z, d0);
                d0 = fmaf(r0w, kv.w, d0);
                float d1 = fmaf(r1x, kv.x, t1);
                d1 = fmaf(r1y, kv.y, d1);
                d1 = fmaf(r1z, kv.z, d1);
                d1 = fmaf(r1w, kv.w, d1);
                d0 += __shfl_xor_sync(0xffffffffu, d0, 4);
                d0 += __shfl_xor_sync(0xffffffffu, d0, 2);
                d0 += __shfl_xor_sync(0xffffffffu, d0, 1);
                d1 += __shfl_xor_sync(0xffffffffu, d1, 4);
                d1 += __shfl_xor_sync(0xffffffffu, d1, 2);
                d1 += __shfl_xor_sync(0xffffffffu, d1, 1);
                l0[s] = d0 * gw[s];
                l1[s] = d1 * gw[s];
            }

            float m0 = l0[0], m1 = l1[0];
            #pragma unroll
            for (int s = 1; s < SEQ; s++) { m0 = fmaxf(m0, l0[s]); m1 = fmaxf(m1, l1[s]); }
            float sum0 = 0.f, sum1 = 0.f;
            #pragma unroll
            for (int s = 0; s < SEQ; s++) {
                l0[s] = __expf(l0[s] - m0); sum0 += l0[s];
                l1[s] = __expf(l1[s] - m1); sum1 += l1[s];
            }
            float inv0 = __frcp_rn(sum0), inv1 = __frcp_rn(sum1);

            // packed V accumulation: {x,y},{z,w} pairs per head
            u64 a0p0 = 0, a0p1 = 0, a1p0 = 0, a1p1 = 0;
            #pragma unroll
            for (int s = 0; s < SEQ; s++) {
                ulonglong2 vv = vptr[(size_t)bl * 72 + s * 8 + o];
                u64 p0d, p1d;
                PACK2(p0d, l0[s], l0[s]);
                PACK2(p1d, l1[s], l1[s]);
                FMA2(a0p0, p0d, vv.x, a0p0);
                FMA2(a0p1, p0d, vv.y, a0p1);
                FMA2(a1p0, p1d, vv.x, a1p0);
                FMA2(a1p1, p1d, vv.y, a1p1);
            }
            u64 i0d, i1d;
            PACK2(i0d, inv0, inv0);
            PACK2(i1d, inv1, inv1);
            MUL2(a0p0, a0p0, i0d);
            MUL2(a0p1, a0p1, i0d);
            MUL2(a1p0, a1p0, i1d);
            MUL2(a1p1, a1p1, i1d);
            if (half) { vB0[0] = a0p0; vB0[1] = a0p1; vB1[0] = a1p0; vB1[1] = a1p1; }
            else      { vA0[0] = a0p0; vA0[1] = a0p1; vA1[0] = a1p0; vA1[1] = a1p1; }
        }

        // ---- stage vs (natural layout; head0 reuses q region) ----
        __syncwarp();
        *(ulonglong2*)&st0reg[trow * 36 + o * 4]       = make_ulonglong2(vA0[0], vA0[1]);
        *(ulonglong2*)&st0reg[144 + trow * 36 + o * 4] = make_ulonglong2(vB0[0], vB0[1]);
        *(ulonglong2*)&st1reg[trow * 36 + o * 4]       = make_ulonglong2(vA1[0], vA1[1]);
        *(ulonglong2*)&st1reg[144 + trow * 36 + o * 4] = make_ulonglong2(vB1[0], vB1[1]);
        __syncwarp();

        // ---- M matvec: f32x2 over g-pairs, weights non-duplicated ----
        u64 oA[4], oB[4];
        #pragma unroll
        for (int fi = 0; fi < 4; fi++) {
            float dd = sD[o * 4 + fi];
            PACK2(oA[fi], dd, 0.0f);
            PACK2(oB[fi], dd, 0.0f);
        }
        #pragma unroll
        for (int j = 0; j < 8; j++) {
            ulonglong2 VA0 = *(const ulonglong2*)&st0reg[trow * 36 + j * 4];
            ulonglong2 VB0 = *(const ulonglong2*)&st0reg[144 + trow * 36 + j * 4];
            ulonglong2 VA1 = *(const ulonglong2*)&st1reg[trow * 36 + j * 4];
            ulonglong2 VB1 = *(const ulonglong2*)&st1reg[144 + trow * 36 + j * 4];
            #pragma unroll
            for (int fi = 0; fi < 4; fi++) {
                ulonglong2 W0 = *(const ulonglong2*)&sMB[j * 128 + fi * 32 + o * 4];
                ulonglong2 W1 = *(const ulonglong2*)&sMB[1024 + j * 128 + fi * 32 + o * 4];
                FMA2(oA[fi], W0.x, VA0.x, oA[fi]);
                FMA2(oA[fi], W0.y, VA0.y, oA[fi]);
                FMA2(oA[fi], W1.x, VA1.x, oA[fi]);
                FMA2(oA[fi], W1.y, VA1.y, oA[fi]);
                FMA2(oB[fi], W0.x, VB0.x, oB[fi]);
                FMA2(oB[fi], W0.y, VB0.y, oB[fi]);
                FMA2(oB[fi], W1.x, VB1.x, oB[fi]);
                FMA2(oB[fi], W1.y, VB1.y, oB[fi]);
            }
        }
        float ovA[4], ovB[4];
        #pragma unroll
        for (int fi = 0; fi < 4; fi++) {
            float lo, hi;
            UNPACK2(lo, hi, oA[fi]); ovA[fi] = lo + hi;
            UNPACK2(lo, hi, oB[fi]); ovB[fi] = lo + hi;
        }

        if (bA < n) optr[(size_t)bA * 8 + o] = make_float4(ovA[0], ovA[1], ovA[2], ovA[3]);
        if (bB < n) optr[(size_t)bB * 8 + o] = make_float4(ovB[0], ovB[1], ovB[2], ovB[3]);
    }
}

extern "C" void kernel_launch(void* const* d_in, const int* in_sizes, int n_in,
                              void* d_out, int out_size) {
    const float* query = (const float*)d_in[0];
    const float* key   = (const float*)d_in[1];
    const float* value = (const float*)d_in[2];
    const float* gauss = (const float*)d_in[3];
    const float* ipw   = (const float*)d_in[4];
    const float* ipb   = (const float*)d_in[5];
    const float* opw   = (const float*)d_in[6];
    const float* opb   = (const float*)d_in[7];
    float* out = (float*)d_out;

    int n = in_sizes[0] / 32;   // N batch elements (T=1, E=32)

    prep_kernel<<<1, 256>>>(ipw, ipb, opw, opb);
    attn_kernel<<<888, 128>>>(query, key, value, gauss, out, n);
}

// round 15
// speedup vs baseline: 1.0787x; 1.0787x over previous
#include <cuda_runtime.h>

// Fused gauss-attention, N=262144, T=1, S=9, E=32, H=2, HD=16.
// Round 15: attn kernel frozen at round-12 best (151.8us ncu: 7 blocks/SM,
// 72 regs, t-fold, scalar butterflies, grid 1036). Single change: prep_kernel
// parallelized from 1 block to 8 blocks x 256 (one merged-weight output per
// thread) to shrink the ~14us non-attn gap between bench and ncu time.

#define SEQ 9
typedef unsigned long long u64;

#define PACK2(out, lo, hi) \
    asm("mov.b64 %0, {%1, %2};" : "=l"(out) : "f"(lo), "f"(hi))
#define UNPACK2(lo, hi, in) \
    asm("mov.b64 {%0, %1}, %2;" : "=f"(lo), "=f"(hi) : "l"(in))
#define FMA2(d, a, b, c) \
    asm("fma.rn.f32x2 %0, %1, %2, %3;" : "=l"(d) : "l"(a), "l"(b), "l"(c))
#define MUL2(d, a, b) \
    asm("mul.rn.f32x2 %0, %1, %2;" : "=l"(d) : "l"(a), "l"(b))

// Block layout (non-duplicated), per head 1024 floats:
//   idx = h*1024 + j*128 + gi*32 + o*4 + c,  value = Mat[4o+gi][4j+c]
__device__ float g_PB[2048];
__device__ float g_MB[2048];
__device__ float g_rb[2 * 32];
__device__ float g_u[2 * 32];
__device__ float g_t0[2];
__device__ float g_D[32];

__global__ void prep_kernel(const float* __restrict__ ipw,
                            const float* __restrict__ ipb,
                            const float* __restrict__ opw,
                            const float* __restrict__ opb) {
    const float* wq = ipw;
    const float* wk = ipw + 1024;
    const float* wv = ipw + 2048;
    const float* bq = ipb;
    const float* bk = ipb + 32;
    const float* bv = ipb + 64;
    int idx = blockIdx.x * 256 + threadIdx.x;   // 0..2047, one output each

    {
        int h = idx >> 10;
        int a = (idx >> 5) & 31;   // row (P: g, M: f)
        int c = idx & 31;          // col (P: e, M: g)
        float accP = 0.f, accM = 0.f;
        #pragma unroll
        for (int d = 0; d < 16; d++) {
            int f = h * 16 + d;
            accP += wk[f * 32 + a] * wq[f * 32 + c];
            accM += opw[a * 32 + f] * wv[f * 32 + c];
        }
        int blk = h * 1024 + (c >> 2) * 128 + (a & 3) * 32 + (a >> 2) * 4 + (c & 3);
        g_PB[blk] = 0.25f * accP;
        g_MB[blk] = accM;
    }

    if (blockIdx.x == 0) {
        int tid = threadIdx.x;
        if (tid < 64) {
            int h = tid >> 5, j = tid & 31;
            float arb = 0.f, au = 0.f;
            #pragma unroll
            for (int d = 0; d < 16; d++) {
                int f = h * 16 + d;
                arb += bq[f] * wk[f * 32 + j];
                au  += wq[f * 32 + j] * bk[f];
            }
            g_rb[tid] = 0.25f * arb;
            g_u[tid]  = 0.25f * au;
        }
        if (tid < 32) {
            float acc = opb[tid];
            #pragma unroll
            for (int e = 0; e < 32; e++) acc += opw[tid * 32 + e] * bv[e];
            g_D[tid] = acc;
        }
        if (tid < 2) {
            float acc = 0.f;
            #pragma unroll
            for (int d = 0; d < 16; d++) acc += bq[tid * 16 + d] * bk[tid * 16 + d];
            g_t0[tid] = 0.25f * acc;
        }
    }
}

__global__ void __launch_bounds__(128, 7)
attn_kernel(const float* __restrict__ query, const float* __restrict__ key,
            const float* __restrict__ value, const float* __restrict__ gauss,
            float* __restrict__ out, int n) {
    __shared__ __align__(16) float sPB[2048];
    __shared__ __align__(16) float sMB[2048];
    // Per-warp staging (natural layout): region0 = q, reused as vs-head0;
    // region1 = vs-head1. Layout [quad][trow][36] per region.
    __shared__ __align__(16) float sStage[4][576];
    __shared__ __align__(16) float sGauss[4][72];
    __shared__ float srb[64];
    __shared__ float su[64];
    __shared__ float st0[2];
    __shared__ float sD[32];

    int tid = threadIdx.x;
    for (int i = tid; i < 2048; i += 128) {
        sPB[i] = g_PB[i];
        sMB[i] = g_MB[i];
    }
    if (tid < 64) { srb[tid] = g_rb[tid]; su[tid] = g_u[tid]; }
    if (tid < 32) sD[tid] = g_D[tid];
    if (tid < 2)  st0[tid] = g_t0[tid];
    __syncthreads();

    const int lane = tid & 31;
    const int o    = lane & 7;      // feature-chunk owner within octet
    const int trow = lane >> 3;     // which batch of the quad
    const int warp = tid >> 5;
    float* st0reg = sStage[warp];         // q / vs-head0: [quad][trow][36]
    float* st1reg = sStage[warp] + 288;   // vs-head1
    float* gb     = sGauss[warp];

    const float4* qptr = (const float4*)query;
    const float4* kptr = (const float4*)key;
    const ulonglong2* vptr = (const ulonglong2*)value;
    float4* optr = (float4*)out;

    const int ngroups = (n + 7) >> 3;
    const int warp_g  = (blockIdx.x * 128 + tid) >> 5;
    const int wstep   = (gridDim.x * 128) >> 5;

    for (int grp = warp_g; grp < ngroups; grp += wstep) {
        int bA = grp * 8 + trow;
        int bB = bA + 4;
        int blA = bA < n ? bA : n - 1;
        int blB = bB < n ? bB : n - 1;

        // ---- stage gauss for the whole group: 72 contiguous floats ----
        __syncwarp();
        {
            int rem9 = n * SEQ - grp * 72;
            if (rem9 >= 72) {
                if (lane < 18)
                    *(float4*)&gb[lane * 4] =
                        *(const float4*)(gauss + (size_t)grp * 72 + lane * 4);
            } else {
                for (int i = lane; i < 72; i += 32)
                    gb[i] = gauss[(size_t)grp * 72 + (i < rem9 ? i : rem9 - 1)];
            }
        }

        // ---- load q chunks (coalesced) ----
        float4 qA = qptr[(size_t)blA * 8 + o];
        float4 qB = qptr[(size_t)blB * 8 + o];

        // per-lane t partials (own chunk); lane o==0 also carries st0 constant
        float c0 = (o == 0) ? st0[0] : 0.0f;
        float c1 = (o == 0) ? st0[1] : 0.0f;
        float tA0 = c0 + su[o * 4 + 0] * qA.x + su[o * 4 + 1] * qA.y
                  + su[o * 4 + 2] * qA.z + su[o * 4 + 3] * qA.w;
        float tA1 = c1 + su[32 + o * 4 + 0] * qA.x + su[32 + o * 4 + 1] * qA.y
                  + su[32 + o * 4 + 2] * qA.z + su[32 + o * 4 + 3] * qA.w;
        float tB0 = c0 + su[o * 4 + 0] * qB.x + su[o * 4 + 1] * qB.y
                  + su[o * 4 + 2] * qB.z + su[o * 4 + 3] * qB.w;
        float tB1 = c1 + su[32 + o * 4 + 0] * qB.x + su[32 + o * 4 + 1] * qB.y
                  + su[32 + o * 4 + 2] * qB.z + su[32 + o * 4 + 3] * qB.w;

        // ---- stage q (natural layout) ----
        *(float4*)&st0reg[trow * 36 + o * 4]       = qA;   // quad A
        *(float4*)&st0reg[144 + trow * 36 + o * 4] = qB;   // quad B
        __syncwarp();

        // ---- P matvec: f32x2 over e-pairs, weights non-duplicated ----
        u64 pA0[4], pA1[4], pB0[4], pB1[4];
        #pragma unroll
        for (int gi = 0; gi < 4; gi++) {
            float b0 = srb[o * 4 + gi];
            float b1 = srb[32 + o * 4 + gi];
            PACK2(pA0[gi], b0, 0.0f);  PACK2(pB0[gi], b0, 0.0f);
            PACK2(pA1[gi], b1, 0.0f);  PACK2(pB1[gi], b1, 0.0f);
        }
        #pragma unroll
        for (int j = 0; j < 8; j++) {
            ulonglong2 QA = *(const ulonglong2*)&st0reg[trow * 36 + j * 4];
            ulonglong2 QB = *(const ulonglong2*)&st0reg[144 + trow * 36 + j * 4];
            #pragma unroll
            for (int gi = 0; gi < 4; gi++) {
                ulonglong2 W0 = *(const ulonglong2*)&sPB[j * 128 + gi * 32 + o * 4];
                ulonglong2 W1 = *(const ulonglong2*)&sPB[1024 + j * 128 + gi * 32 + o * 4];
                FMA2(pA0[gi], W0.x, QA.x, pA0[gi]);
                FMA2(pA0[gi], W0.y, QA.y, pA0[gi]);
                FMA2(pB0[gi], W0.x, QB.x, pB0[gi]);
                FMA2(pB0[gi], W0.y, QB.y, pB0[gi]);
                FMA2(pA1[gi], W1.x, QA.x, pA1[gi]);
                FMA2(pA1[gi], W1.y, QA.y, pA1[gi]);
                FMA2(pB1[gi], W1.x, QB.x, pB1[gi]);
                FMA2(pB1[gi], W1.y, QB.y, pB1[gi]);
            }
        }
        float rA0[4], rA1[4], rB0[4], rB1[4];
        #pragma unroll
        for (int gi = 0; gi < 4; gi++) {
            float lo, hi;
            UNPACK2(lo, hi, pA0[gi]); rA0[gi] = lo + hi;
            UNPACK2(lo, hi, pA1[gi]); rA1[gi] = lo + hi;
            UNPACK2(lo, hi, pB0[gi]); rB0[gi] = lo + hi;
            UNPACK2(lo, hi, pB1[gi]); rB1[gi] = lo + hi;
        }

        // ---- per-quad: K stream -> logits -> softmax -> V stream ----
        u64 vA0[2], vA1[2], vB0[2], vB1[2];
        #pragma unroll
        for (int half = 0; half < 2; half++) {
            int bl = half ? blB : blA;
            int grow = half * 4 + trow;       // batch index within group
            float r0x = half ? rB0[0] : rA0[0];
            float r0y = half ? rB0[1] : rA0[1];
            float r0z = half ? rB0[2] : rA0[2];
            float r0w = half ? rB0[3] : rA0[3];
            float r1x = half ? rB1[0] : rA1[0];
            float r1y = half ? rB1[1] : rA1[1];
            float r1z = half ? rB1[2] : rA1[2];
            float r1w = half ? rB1[3] : rA1[3];
            float t0 = half ? tB0 : tA0;      // per-lane partial (incl. st0 on o==0)
            float t1 = half ? tB1 : tA1;

            float l0[SEQ], l1[SEQ];
            #pragma unroll
            for (int s = 0; s < SEQ; s++) {
                float4 kv = kptr[(size_t)bl * 72 + s * 8 + o];
                float d0 = fmaf(r0x, kv.x, t0);   // t folded pre-reduction
                d0 = fmaf(r0y, kv.y, d0);
                d0 = fmaf(r0z, kv.z, d0);
                d0 = fmaf(r0w, kv.w, d0);
                float d1 = fmaf(r1x, kv.x, t1);
                d1 = fmaf(r1y, kv.y, d1);
                d1 = fmaf(r1z, kv.z, d1);
                d1 = fmaf(r1w, kv.w, d1);
                d0 += __shfl_xor_sync(0xffffffffu, d0, 4);
                d0 += __shfl_xor_sync(0xffffffffu, d0, 2);
                d0 += __shfl_xor_sync(0xffffffffu, d0, 1);
                d1 += __shfl_xor_sync(0xffffffffu, d1, 4);
                d1 += __shfl_xor_sync(0xffffffffu, d1, 2);
                d1 += __shfl_xor_sync(0xffffffffu, d1, 1);
                float gw = __expf(-10.0f * gb[grow * SEQ + s]);
                l0[s] = d0 * gw;
                l1[s] = d1 * gw;
            }

            float m0 = l0[0], m1 = l1[0];
            #pragma unroll
            for (int s = 1; s < SEQ; s++) { m0 = fmaxf(m0, l0[s]); m1 = fmaxf(m1, l1[s]); }
            float sum0 = 0.f, sum1 = 0.f;
            #pragma unroll
            for (int s = 0; s < SEQ; s++) {
                l0[s] = __expf(l0[s] - m0); sum0 += l0[s];
                l1[s] = __expf(l1[s] - m1); sum1 += l1[s];
            }
            float inv0 = __frcp_rn(sum0), inv1 = __frcp_rn(sum1);

            // packed V accumulation: {x,y},{z,w} pairs per head
            u64 a0p0 = 0, a0p1 = 0, a1p0 = 0, a1p1 = 0;
            #pragma unroll
            for (int s = 0; s < SEQ; s++) {
                ulonglong2 vv = vptr[(size_t)bl * 72 + s * 8 + o];
                u64 p0d, p1d;
                PACK2(p0d, l0[s], l0[s]);
                PACK2(p1d, l1[s], l1[s]);
                FMA2(a0p0, p0d, vv.x, a0p0);
                FMA2(a0p1, p0d, vv.y, a0p1);
                FMA2(a1p0, p1d, vv.x, a1p0);
                FMA2(a1p1, p1d, vv.y, a1p1);
            }
            u64 i0d, i1d;
            PACK2(i0d, inv0, inv0);
            PACK2(i1d, inv1, inv1);
            MUL2(a0p0, a0p0, i0d);
            MUL2(a0p1, a0p1, i0d);
            MUL2(a1p0, a1p0, i1d);
            MUL2(a1p1, a1p1, i1d);
            if (half) { vB0[0] = a0p0; vB0[1] = a0p1; vB1[0] = a1p0; vB1[1] = a1p1; }
            else      { vA0[0] = a0p0; vA0[1] = a0p1; vA1[0] = a1p0; vA1[1] = a1p1; }
        }

        // ---- stage vs (natural layout; head0 reuses q region) ----
        __syncwarp();
        *(ulonglong2*)&st0reg[trow * 36 + o * 4]       = make_ulonglong2(vA0[0], vA0[1]);
        *(ulonglong2*)&st0reg[144 + trow * 36 + o * 4] = make_ulonglong2(vB0[0], vB0[1]);
        *(ulonglong2*)&st1reg[trow * 36 + o * 4]       = make_ulonglong2(vA1[0], vA1[1]);
        *(ulonglong2*)&st1reg[144 + trow * 36 + o * 4] = make_ulonglong2(vB1[0], vB1[1]);
        __syncwarp();

        // ---- M matvec: f32x2 over g-pairs, weights non-duplicated ----
        u64 oA[4], oB[4];
        #pragma unroll
        for (int fi = 0; fi < 4; fi++) {
            float dd = sD[o * 4 + fi];
            PACK2(oA[fi], dd, 0.0f);
            PACK2(oB[fi], dd, 0.0f);
        }
        #pragma unroll
        for (int j = 0; j < 8; j++) {
            ulonglong2 VA0 = *(const ulonglong2*)&st0reg[trow * 36 + j * 4];
            ulonglong2 VB0 = *(const ulonglong2*)&st0reg[144 + trow * 36 + j * 4];
            ulonglong2 VA1 = *(const ulonglong2*)&st1reg[trow * 36 + j * 4];
            ulonglong2 VB1 = *(const ulonglong2*)&st1reg[144 + trow * 36 + j * 4];
            #pragma unroll
            for (int fi = 0; fi < 4; fi++) {
                ulonglong2 W0 = *(const ulonglong2*)&sMB[j * 128 + fi * 32 + o * 4];
                ulonglong2 W1 = *(const ulonglong2*)&sMB[1024 + j * 128 + fi * 32 + o * 4];
                FMA2(oA[fi], W0.x, VA0.x, oA[fi]);
                FMA2(oA[fi], W0.y, VA0.y, oA[fi]);
                FMA2(oA[fi], W1.x, VA1.x, oA[fi]);
                FMA2(oA[fi], W1.y, VA1.y, oA[fi]);
                FMA2(oB[fi], W0.x, VB0.x, oB[fi]);
                FMA2(oB[fi], W0.y, VB0.y, oB[fi]);
                FMA2(oB[fi], W1.x, VB1.x, oB[fi]);
                FMA2(oB[fi], W1.y, VB1.y, oB[fi]);
            }
        }
        float ovA[4], ovB[4];
        #pragma unroll
        for (int fi = 0; fi < 4; fi++) {
            float lo, hi;
            UNPACK2(lo, hi, oA[fi]); ovA[fi] = lo + hi;
            UNPACK2(lo, hi, oB[fi]); ovB[fi] = lo + hi;
        }

        if (bA < n) optr[(size_t)bA * 8 + o] = make_float4(ovA[0], ovA[1], ovA[2], ovA[3]);
        if (bB < n) optr[(size_t)bB * 8 + o] = make_float4(ovB[0], ovB[1], ovB[2], ovB[3]);
    }
}

extern "C" void kernel_launch(void* const* d_in, const int* in_sizes, int n_in,
                              void* d_out, int out_size) {
    const float* query = (const float*)d_in[0];
    const float* key   = (const float*)d_in[1];
    const float* value = (const float*)d_in[2];
    const float* gauss = (const float*)d_in[3];
    const float* ipw   = (const float*)d_in[4];
    const float* ipb   = (const float*)d_in[5];
    const float* opw   = (const float*)d_in[6];
    const float* opb   = (const float*)d_in[7];
    float* out = (float*)d_out;

    int n = in_sizes[0] / 32;   // N batch elements (T=1, E=32)

    prep_kernel<<<8, 256>>>(ipw, ipb, opw, opb);
    attn_kernel<<<1036, 128>>>(query, key, value, gauss, out, n);
}